// round 2
// baseline (speedup 1.0000x reference)
#include <cuda_runtime.h>

#define B_SZ 1024
#define N_SZ 256
#define D_SZ 256
#define M_SZ 768
#define NEG_VAL -1.0e10f

// Scratch (allocation-free rule: __device__ globals)
__device__ float g_att[B_SZ * M_SZ];           // attention output per batch (M)
__device__ float g_h[B_SZ * M_SZ];             // fc output + residual
__device__ float g_x[B_SZ * (M_SZ + D_SZ)];    // [LN(h), src]
__device__ float g_y[B_SZ * M_SZ];             // relu(x @ W1^T)

// ---------------------------------------------------------------------------
// K1: fused single-pass attention with online softmax.
// One CTA per batch. k rows staged 8 at a time in SMEM; each tile is read from
// HBM exactly once and used for both the score dot and the weighted-sum
// accumulation.
// ---------------------------------------------------------------------------
__global__ __launch_bounds__(256) void attn_kernel(
    const float* __restrict__ seq, const float* __restrict__ seq_e,
    const float* __restrict__ seq_t, const unsigned int* __restrict__ mask,
    const float* __restrict__ shared_attn, float* __restrict__ attn_w_out)
{
    __shared__ float sK[8][M_SZ];      // 24 KB tile: 8 rows of concat(seq,seq_e,seq_t)
    __shared__ float wk_s[M_SZ];
    __shared__ float s_all[N_SZ];
    __shared__ float ts[8];

    const int b    = blockIdx.x;
    const int tid  = threadIdx.x;
    const int lane = tid & 31;
    const int wrp  = tid >> 5;

    // wk = shared_attn[0, M:2M]
    wk_s[tid]       = shared_attn[M_SZ + tid];
    wk_s[tid + 256] = shared_attn[M_SZ + tid + 256];
    wk_s[tid + 512] = shared_attn[M_SZ + tid + 512];

    float a0 = 0.f, a1 = 0.f, a2 = 0.f;   // thread owns feature dims tid, tid+256, tid+512
    float lsum = 0.f, mval = -3.0e38f;

    const size_t bbase = (size_t)b * N_SZ * D_SZ;

    for (int t = 0; t < N_SZ / 8; t++) {
        const int n0 = t * 8;
        // ---- load 8 rows x 768 floats (coalesced float4) ----
        #pragma unroll
        for (int u = 0; u < 6; u++) {
            int idx = u * 256 + tid;          // float4 index 0..1535
            int r   = idx / 192;
            int pos = idx - r * 192;          // 0..191 (row-local float4)
            int seg = pos >> 6;               // 0: seq, 1: seq_e, 2: seq_t
            int j4  = pos & 63;
            const float* base = (seg == 0) ? seq : ((seg == 1) ? seq_e : seq_t);
            float4 v = __ldg((const float4*)(base + bbase + (size_t)(n0 + r) * D_SZ) + j4);
            ((float4*)sK)[r * 192 + pos] = v;
        }
        __syncthreads();

        // ---- scores: warp w handles row w ----
        float part = 0.f;
        #pragma unroll
        for (int kk = 0; kk < 24; kk++) {
            int e = lane + (kk << 5);
            part += sK[wrp][e] * wk_s[e];
        }
        #pragma unroll
        for (int o = 16; o > 0; o >>= 1)
            part += __shfl_xor_sync(0xffffffffu, part, o);
        if (lane == 0) {
            int n = n0 + wrp;
            float s = (mask[(size_t)b * N_SZ + n] != 0u) ? NEG_VAL : part;
            ts[wrp]   = s;
            s_all[n]  = s;
        }
        __syncthreads();

        // ---- online softmax update (all threads redundantly, deterministic) ----
        float mt = mval;
        #pragma unroll
        for (int r = 0; r < 8; r++) mt = fmaxf(mt, ts[r]);
        if (mt > mval) {
            float sc = __expf(mval - mt);
            a0 *= sc; a1 *= sc; a2 *= sc; lsum *= sc;
            mval = mt;
        }
        #pragma unroll
        for (int r = 0; r < 8; r++) {
            float p = __expf(ts[r] - mval);
            lsum += p;
            a0 += p * sK[r][tid];
            a1 += p * sK[r][tid + 256];
            a2 += p * sK[r][tid + 512];
        }
        __syncthreads();
    }

    float inv = 1.0f / lsum;
    attn_w_out[(size_t)b * N_SZ + tid] = __expf(s_all[tid] - mval) * inv;
    float* o = g_att + (size_t)b * M_SZ;
    o[tid]       = a0 * inv;
    o[tid + 256] = a1 * inv;
    o[tid + 512] = a2 * inv;
}

// ---------------------------------------------------------------------------
// Generic batched-matvec GEMM core: C[b][i] = epi( sum_j A[b][j] * W[i][j] ).
// Block = 16 batches x 256 outputs. A tile in SMEM (broadcast reads), W rows
// streamed from L2 (each weight matrix fits in L2; reused by all 64 b-tiles).
// ---------------------------------------------------------------------------
template <int KD, int EPI>
__device__ __forceinline__ void gemm_core(
    const float* __restrict__ A, const float* __restrict__ W,
    float* __restrict__ C, int cstride,
    const float* __restrict__ e0, const float* __restrict__ e1)
{
    __shared__ float4 sA[16][32];      // 16 batches x 128 floats
    const int tid = threadIdx.x;
    const int i   = blockIdx.y * 256 + tid;
    const int gb0 = blockIdx.x * 16;

    float acc[16];
    #pragma unroll
    for (int bb = 0; bb < 16; bb++) acc[bb] = 0.f;

    const float* wrow = W + (size_t)i * KD;

    for (int jt = 0; jt < KD; jt += 128) {
        #pragma unroll
        for (int u = 0; u < 2; u++) {
            int idx = u * 256 + tid;   // 0..511 float4
            int r = idx >> 5;
            int c = idx & 31;
            sA[r][c] = __ldg((const float4*)(A + (size_t)(gb0 + r) * KD + jt) + c);
        }
        __syncthreads();

        #pragma unroll 4
        for (int j4 = 0; j4 < 32; j4++) {
            float4 wv = __ldg((const float4*)(wrow + jt) + j4);
            #pragma unroll
            for (int bb = 0; bb < 16; bb++) {
                float4 av = sA[bb][j4];
                acc[bb] = fmaf(wv.x, av.x, acc[bb]);
                acc[bb] = fmaf(wv.y, av.y, acc[bb]);
                acc[bb] = fmaf(wv.z, av.z, acc[bb]);
                acc[bb] = fmaf(wv.w, av.w, acc[bb]);
            }
        }
        __syncthreads();
    }

    #pragma unroll
    for (int bb = 0; bb < 16; bb++) {
        float v = acc[bb];
        int gb = gb0 + bb;
        if (EPI == 0) {
            // residual add of q = [src, 0, src_t]; uniform per blockIdx.y
            if (blockIdx.y == 0)      v += e0[(size_t)gb * 256 + tid];
            else if (blockIdx.y == 2) v += e1[(size_t)gb * 256 + tid];
        } else if (EPI == 1) {
            v = fmaxf(v, 0.f);
        }
        C[(size_t)gb * cstride + i] = v;
    }
}

__global__ __launch_bounds__(256) void gemm_fc_kernel(
    const float* __restrict__ fc_w, const float* __restrict__ src,
    const float* __restrict__ src_t)
{
    gemm_core<768, 0>(g_att, fc_w, g_h, 768, src, src_t);
}

__global__ __launch_bounds__(256) void gemm_w1_kernel(const float* __restrict__ w1)
{
    gemm_core<1024, 1>(g_x, w1, g_y, 768, nullptr, nullptr);
}

__global__ __launch_bounds__(256) void gemm_w2_kernel(
    const float* __restrict__ w2, float* __restrict__ out)
{
    gemm_core<768, 2>(g_y, w2, out, 256, nullptr, nullptr);
}

// ---------------------------------------------------------------------------
// K3: LayerNorm over M=768 + concat with src into g_x. One CTA per batch.
// Two-pass (mean, then centered variance) matching the reference formula.
// ---------------------------------------------------------------------------
__global__ __launch_bounds__(256) void ln_concat_kernel(
    const float* __restrict__ ln_w, const float* __restrict__ ln_b,
    const float* __restrict__ src)
{
    __shared__ float red[8];
    const int b    = blockIdx.x;
    const int tid  = threadIdx.x;
    const int lane = tid & 31, wrp = tid >> 5;

    const float* h = g_h + (size_t)b * M_SZ;
    float x0 = h[tid], x1 = h[tid + 256], x2 = h[tid + 512];

    float s = x0 + x1 + x2;
    #pragma unroll
    for (int o = 16; o > 0; o >>= 1) s += __shfl_xor_sync(0xffffffffu, s, o);
    if (lane == 0) red[wrp] = s;
    __syncthreads();
    float tot = red[0] + red[1] + red[2] + red[3] + red[4] + red[5] + red[6] + red[7];
    float mu  = tot * (1.0f / 768.0f);
    __syncthreads();

    float d0 = x0 - mu, d1 = x1 - mu, d2 = x2 - mu;
    float q = d0 * d0 + d1 * d1 + d2 * d2;
    #pragma unroll
    for (int o = 16; o > 0; o >>= 1) q += __shfl_xor_sync(0xffffffffu, q, o);
    if (lane == 0) red[wrp] = q;
    __syncthreads();
    float tot2 = red[0] + red[1] + red[2] + red[3] + red[4] + red[5] + red[6] + red[7];
    float rstd = rsqrtf(tot2 * (1.0f / 768.0f) + 1e-5f);

    float* xo = g_x + (size_t)b * (M_SZ + D_SZ);
    xo[tid]        = d0 * rstd * ln_w[tid]       + ln_b[tid];
    xo[tid + 256]  = d1 * rstd * ln_w[tid + 256] + ln_b[tid + 256];
    xo[tid + 512]  = d2 * rstd * ln_w[tid + 512] + ln_b[tid + 512];
    xo[768 + tid]  = src[(size_t)b * 256 + tid];   // concat src
}

// ---------------------------------------------------------------------------
extern "C" void kernel_launch(void* const* d_in, const int* in_sizes, int n_in,
                              void* d_out, int out_size)
{
    const float* src         = (const float*)d_in[0];
    const float* src_t       = (const float*)d_in[1];
    const float* seq         = (const float*)d_in[2];
    const float* seq_t       = (const float*)d_in[3];
    const float* seq_e       = (const float*)d_in[4];
    const unsigned int* mask = (const unsigned int*)d_in[5];
    const float* shared_attn = (const float*)d_in[6];
    const float* fc_w        = (const float*)d_in[7];
    const float* ln_w        = (const float*)d_in[8];
    const float* ln_b        = (const float*)d_in[9];
    const float* w1          = (const float*)d_in[10];
    const float* w2          = (const float*)d_in[11];

    float* out    = (float*)d_out;                    // (B, D) = first 262144
    float* attn_w = out + (size_t)B_SZ * D_SZ;        // (B, N) = next 262144

    // k = concat([seq, seq_e, seq_t]) — note seq_e before seq_t.
    attn_kernel<<<B_SZ, 256>>>(seq, seq_e, seq_t, mask, shared_attn, attn_w);
    gemm_fc_kernel<<<dim3(64, 3), 256>>>(fc_w, src, src_t);
    ln_concat_kernel<<<B_SZ, 256>>>(ln_w, ln_b, src);
    gemm_w1_kernel<<<dim3(64, 3), 256>>>(w1);
    gemm_w2_kernel<<<dim3(64, 1), 256>>>(w2, out);
}

// round 4
// speedup vs baseline: 1.9685x; 1.9685x over previous
#include <cuda_runtime.h>
#include <cstdint>

#define B_SZ 1024
#define N_SZ 256
#define D_SZ 256
#define M_SZ 768
#define NEG_VAL -1.0e10f

// Scratch (__device__ globals; no allocation allowed)
__device__ float g_att[B_SZ * M_SZ];              // attention output (B, 768)
__device__ float g_x[B_SZ * (M_SZ + D_SZ)];       // [LN(h), src]  (B, 1024)
__device__ float g_y[B_SZ * M_SZ];                // relu(x @ W1^T)
__device__ float g_part[3 * B_SZ * M_SZ];         // split-K partials (max 3*1024*768)

// ---------------------------------------------------------------------------
// K1: fused single-pass attention, online softmax, cp.async double-buffered.
// One CTA per batch; 16-row k-tiles; k read from HBM exactly once.
// ---------------------------------------------------------------------------
#define TROWS 16
#define ATTN_SMEM ((2 * TROWS * M_SZ + M_SZ + N_SZ + TROWS) * 4)

__device__ __forceinline__ void cp_async16(uint32_t saddr, const void* gaddr) {
    asm volatile("cp.async.cg.shared.global [%0], [%1], 16;\n" :: "r"(saddr), "l"(gaddr));
}
__device__ __forceinline__ void cp_commit() { asm volatile("cp.async.commit_group;\n"); }

__global__ __launch_bounds__(256) void attn_kernel(
    const float* __restrict__ seq, const float* __restrict__ seq_e,
    const float* __restrict__ seq_t, const unsigned int* __restrict__ mask,
    const float* __restrict__ shared_attn, float* __restrict__ attn_w_out)
{
    extern __shared__ float smem[];
    float* sK    = smem;                       // [2][TROWS][768]
    float* s_all = smem + 2 * TROWS * M_SZ;    // [256]
    float* ts    = s_all + N_SZ;               // [TROWS]

    const int b    = blockIdx.x;
    const int tid  = threadIdx.x;
    const int lane = tid & 31;
    const int wrp  = tid >> 5;
    const size_t bbase = (size_t)b * N_SZ * D_SZ;

    // wk into registers: lane needs wk[lane + 32*kk]
    float w_r[24];
    #pragma unroll
    for (int kk = 0; kk < 24; kk++)
        w_r[kk] = __ldg(shared_attn + M_SZ + lane + (kk << 5));

    float a0 = 0.f, a1 = 0.f, a2 = 0.f;
    float lsum = 0.f, mval = -3.0e38f;

    // issue tile 0
    {
        #pragma unroll
        for (int u = 0; u < 12; u++) {
            int idx = u * 256 + tid;           // 0..3071 float4
            int r   = idx / 192;
            int pos = idx - r * 192;
            int seg = pos >> 6;
            int j4  = pos & 63;
            const float* base = (seg == 0) ? seq : ((seg == 1) ? seq_e : seq_t);
            uint32_t sa = (uint32_t)__cvta_generic_to_shared(sK + (r * 192 + pos) * 4);
            cp_async16(sa, base + bbase + (size_t)r * D_SZ + j4 * 4);
        }
        cp_commit();
    }

    for (int t = 0; t < N_SZ / TROWS; t++) {
        const int cur = t & 1;
        if (t + 1 < N_SZ / TROWS) {
            const int nxt = (t + 1) & 1;
            const int n0n = (t + 1) * TROWS;
            #pragma unroll
            for (int u = 0; u < 12; u++) {
                int idx = u * 256 + tid;
                int r   = idx / 192;
                int pos = idx - r * 192;
                int seg = pos >> 6;
                int j4  = pos & 63;
                const float* base = (seg == 0) ? seq : ((seg == 1) ? seq_e : seq_t);
                uint32_t sa = (uint32_t)__cvta_generic_to_shared(
                    sK + (nxt * TROWS * M_SZ) + (r * 192 + pos) * 4);
                cp_async16(sa, base + bbase + (size_t)(n0n + r) * D_SZ + j4 * 4);
            }
            cp_commit();
            asm volatile("cp.async.wait_group 1;\n");
        } else {
            asm volatile("cp.async.wait_group 0;\n");
        }
        __syncthreads();

        const float* kb = sK + cur * TROWS * M_SZ;
        const int n0 = t * TROWS;

        // scores: each warp handles 2 rows
        {
            const int r0 = wrp * 2;
            float p0 = 0.f, p1 = 0.f;
            #pragma unroll
            for (int kk = 0; kk < 24; kk++) {
                int e = lane + (kk << 5);
                float w = w_r[kk];
                p0 = fmaf(kb[r0 * M_SZ + e], w, p0);
                p1 = fmaf(kb[(r0 + 1) * M_SZ + e], w, p1);
            }
            #pragma unroll
            for (int o = 16; o > 0; o >>= 1) {
                p0 += __shfl_xor_sync(0xffffffffu, p0, o);
                p1 += __shfl_xor_sync(0xffffffffu, p1, o);
            }
            if (lane == 0) {
                float s0 = (mask[(size_t)b * N_SZ + n0 + r0] != 0u)     ? NEG_VAL : p0;
                float s1 = (mask[(size_t)b * N_SZ + n0 + r0 + 1] != 0u) ? NEG_VAL : p1;
                ts[r0] = s0;        ts[r0 + 1] = s1;
                s_all[n0 + r0] = s0; s_all[n0 + r0 + 1] = s1;
            }
        }
        __syncthreads();

        // online softmax update (redundant per-thread, deterministic)
        float mt = mval;
        #pragma unroll
        for (int r = 0; r < TROWS; r++) mt = fmaxf(mt, ts[r]);
        if (mt > mval) {
            float sc = __expf(mval - mt);
            a0 *= sc; a1 *= sc; a2 *= sc; lsum *= sc;
            mval = mt;
        }
        #pragma unroll
        for (int r = 0; r < TROWS; r++) {
            float p = __expf(ts[r] - mval);
            lsum += p;
            const float* kr = kb + r * M_SZ;
            a0 = fmaf(p, kr[tid],       a0);
            a1 = fmaf(p, kr[tid + 256], a1);
            a2 = fmaf(p, kr[tid + 512], a2);
        }
        __syncthreads();   // protect sK[cur] before next-next issue overwrites it
    }

    float inv = 1.0f / lsum;
    attn_w_out[(size_t)b * N_SZ + tid] = __expf(s_all[tid] - mval) * inv;
    float* o = g_att + (size_t)b * M_SZ;
    o[tid]       = a0 * inv;
    o[tid + 256] = a1 * inv;
    o[tid + 512] = a2 * inv;
}

// ---------------------------------------------------------------------------
// Split-K SIMT GEMM: C_part[z][b][n] = sum_{k in chunk z} A[b][k] * W[n][k]
// Tile 128 batches x 64 outputs, Kt=32, micro 8x4 (strided: m=ty+16i, n=tx+16e)
// Conflict-free SMEM: rows padded to 33 floats.
// ---------------------------------------------------------------------------
template <int KD, int S>
__global__ __launch_bounds__(256, 2) void gemm_sk_kernel(
    const float* __restrict__ A, const float* __restrict__ W,
    float* __restrict__ part, int Nout)
{
    __shared__ float sA[128 * 33];
    __shared__ float sW[64 * 33];

    const int tid = threadIdx.x;
    const int tx = tid & 15, ty = tid >> 4;
    const int m0 = blockIdx.x * 128;
    const int n0 = blockIdx.y * 64;
    const int z  = blockIdx.z;
    constexpr int KT = KD / 32;
    const int kt0 = z * KT / S;
    const int kt1 = (z + 1) * KT / S;

    float acc[8][4];
    #pragma unroll
    for (int i = 0; i < 8; i++)
        #pragma unroll
        for (int e = 0; e < 4; e++) acc[i][e] = 0.f;

    for (int kt = kt0; kt < kt1; kt++) {
        const int kc = kt * 32;
        #pragma unroll
        for (int u = 0; u < 4; u++) {
            int idx = u * 256 + tid;
            int r = idx >> 3, j4 = idx & 7;
            float4 v = __ldg((const float4*)(A + (size_t)(m0 + r) * KD + kc) + j4);
            float* d = sA + r * 33 + j4 * 4;
            d[0] = v.x; d[1] = v.y; d[2] = v.z; d[3] = v.w;
        }
        #pragma unroll
        for (int u = 0; u < 2; u++) {
            int idx = u * 256 + tid;
            int r = idx >> 3, j4 = idx & 7;
            float4 v = __ldg((const float4*)(W + (size_t)(n0 + r) * KD + kc) + j4);
            float* d = sW + r * 33 + j4 * 4;
            d[0] = v.x; d[1] = v.y; d[2] = v.z; d[3] = v.w;
        }
        __syncthreads();

        #pragma unroll 8
        for (int k = 0; k < 32; k++) {
            float wv[4], av[8];
            #pragma unroll
            for (int e = 0; e < 4; e++) wv[e] = sW[(tx + 16 * e) * 33 + k];
            #pragma unroll
            for (int i = 0; i < 8; i++) av[i] = sA[(ty + 16 * i) * 33 + k];
            #pragma unroll
            for (int i = 0; i < 8; i++)
                #pragma unroll
                for (int e = 0; e < 4; e++)
                    acc[i][e] = fmaf(av[i], wv[e], acc[i][e]);
        }
        __syncthreads();
    }

    float* p = part + (size_t)z * B_SZ * Nout;
    #pragma unroll
    for (int i = 0; i < 8; i++)
        #pragma unroll
        for (int e = 0; e < 4; e++)
            p[(size_t)(m0 + ty + 16 * i) * Nout + n0 + tx + 16 * e] = acc[i][e];
}

// ---------------------------------------------------------------------------
// Reduce kernels (fold split-K partials + epilogue)
// ---------------------------------------------------------------------------
__global__ __launch_bounds__(256) void reduce_fc_ln_kernel(
    const float* __restrict__ src, const float* __restrict__ src_t,
    const float* __restrict__ ln_w, const float* __restrict__ ln_b)
{
    __shared__ float red[8];
    const int b = blockIdx.x;
    const int tid = threadIdx.x;
    const int lane = tid & 31, wrp = tid >> 5;

    const float* p0 = g_part + (size_t)b * M_SZ;
    const float* p1 = p0 + (size_t)B_SZ * M_SZ;
    const float* p2 = p1 + (size_t)B_SZ * M_SZ;

    float x0 = p0[tid]       + p1[tid]       + p2[tid]       + src[(size_t)b * D_SZ + tid];
    float x1 = p0[tid + 256] + p1[tid + 256] + p2[tid + 256];
    float x2 = p0[tid + 512] + p1[tid + 512] + p2[tid + 512] + src_t[(size_t)b * D_SZ + tid];

    float s = x0 + x1 + x2;
    #pragma unroll
    for (int o = 16; o > 0; o >>= 1) s += __shfl_xor_sync(0xffffffffu, s, o);
    if (lane == 0) red[wrp] = s;
    __syncthreads();
    float mu = (red[0]+red[1]+red[2]+red[3]+red[4]+red[5]+red[6]+red[7]) * (1.0f/768.0f);
    __syncthreads();

    float d0 = x0 - mu, d1 = x1 - mu, d2 = x2 - mu;
    float q = d0*d0 + d1*d1 + d2*d2;
    #pragma unroll
    for (int o = 16; o > 0; o >>= 1) q += __shfl_xor_sync(0xffffffffu, q, o);
    if (lane == 0) red[wrp] = q;
    __syncthreads();
    float var = (red[0]+red[1]+red[2]+red[3]+red[4]+red[5]+red[6]+red[7]) * (1.0f/768.0f);
    float rstd = rsqrtf(var + 1e-5f);

    float* xo = g_x + (size_t)b * (M_SZ + D_SZ);
    xo[tid]       = d0 * rstd * ln_w[tid]       + ln_b[tid];
    xo[tid + 256] = d1 * rstd * ln_w[tid + 256] + ln_b[tid + 256];
    xo[tid + 512] = d2 * rstd * ln_w[tid + 512] + ln_b[tid + 512];
    xo[768 + tid] = src[(size_t)b * D_SZ + tid];
}

__global__ __launch_bounds__(256) void reduce_relu_kernel()
{
    const int b = blockIdx.x;
    const int tid = threadIdx.x;
    const float* p0 = g_part + (size_t)b * M_SZ;
    const float* p1 = p0 + (size_t)B_SZ * M_SZ;
    const float* p2 = p1 + (size_t)B_SZ * M_SZ;
    float* y = g_y + (size_t)b * M_SZ;
    #pragma unroll
    for (int c = 0; c < 3; c++) {
        int f = tid + c * 256;
        y[f] = fmaxf(p0[f] + p1[f] + p2[f], 0.f);
    }
}

__global__ __launch_bounds__(256) void reduce_out_kernel(float* __restrict__ out)
{
    const int b = blockIdx.x;
    const int tid = threadIdx.x;
    float s = 0.f;
    #pragma unroll
    for (int z = 0; z < 8; z++)
        s += g_part[(size_t)z * B_SZ * D_SZ + (size_t)b * D_SZ + tid];
    out[(size_t)b * D_SZ + tid] = s;
}

// ---------------------------------------------------------------------------
extern "C" void kernel_launch(void* const* d_in, const int* in_sizes, int n_in,
                              void* d_out, int out_size)
{
    const float* src         = (const float*)d_in[0];
    const float* src_t       = (const float*)d_in[1];
    const float* seq         = (const float*)d_in[2];
    const float* seq_t       = (const float*)d_in[3];
    const float* seq_e       = (const float*)d_in[4];
    const unsigned int* mask = (const unsigned int*)d_in[5];
    const float* shared_attn = (const float*)d_in[6];
    const float* fc_w        = (const float*)d_in[7];
    const float* ln_w        = (const float*)d_in[8];
    const float* ln_b        = (const float*)d_in[9];
    const float* w1          = (const float*)d_in[10];
    const float* w2          = (const float*)d_in[11];

    float* out    = (float*)d_out;
    float* attn_w = out + (size_t)B_SZ * D_SZ;

    float* g_att_p;  cudaGetSymbolAddress((void**)&g_att_p, g_att);
    float* g_x_p;    cudaGetSymbolAddress((void**)&g_x_p, g_x);
    float* g_y_p;    cudaGetSymbolAddress((void**)&g_y_p, g_y);
    float* g_part_p; cudaGetSymbolAddress((void**)&g_part_p, g_part);

    cudaFuncSetAttribute(attn_kernel, cudaFuncAttributeMaxDynamicSharedMemorySize, ATTN_SMEM);

    attn_kernel<<<B_SZ, 256, ATTN_SMEM>>>(seq, seq_e, seq_t, mask, shared_attn, attn_w);

    gemm_sk_kernel<768, 3><<<dim3(8, 12, 3), 256>>>(g_att_p, fc_w, g_part_p, M_SZ);
    reduce_fc_ln_kernel<<<B_SZ, 256>>>(src, src_t, ln_w, ln_b);

    gemm_sk_kernel<1024, 3><<<dim3(8, 12, 3), 256>>>(g_x_p, w1, g_part_p, M_SZ);
    reduce_relu_kernel<<<B_SZ, 256>>>();

    gemm_sk_kernel<768, 8><<<dim3(8, 4, 8), 256>>>(g_y_p, w2, g_part_p, D_SZ);
    reduce_out_kernel<<<B_SZ, 256>>>(out);
}